// round 12
// baseline (speedup 1.0000x reference)
#include <cuda_runtime.h>
#include <cuda_bf16.h>
#include <cstdint>

#define B_   512
#define T_   1024
#define H_   256
#define NCTA 256
#define NTH  256
#define STG  32768
#define SMEM_DYN (1024 + 3*STG)

__device__ uint4 g_x_hi[8388608], g_x_lo[8388608];   // [t][512][16 gran]
__device__ uint4 g_w1_hi[49152],  g_w1_lo[49152];    // [n'=1024][48 gran]
__device__ uint4 g_w2_hi[65536],  g_w2_lo[65536];    // [n'=1024][64 gran]
__device__ uint4 g_h1_hi[32768],  g_h1_lo[32768];    // [buf2][512][32 gran]
__device__ uint4 g_h2_hi[32768],  g_h2_lo[32768];
__device__ float g_h2f[B_ * H_];
__device__ unsigned g_bcnt[8 * 32];
__device__ unsigned g_bsense[8 * 32];

__device__ __forceinline__ uint32_t sm32(const void* p) {
    uint32_t a;
    asm("{ .reg .u64 t; cvta.to.shared.u64 t, %1; cvt.u32.u64 %0, t; }" : "=r"(a) : "l"(p));
    return a;
}
__device__ __forceinline__ void cp16(uint32_t d, const void* s) {
    asm volatile("cp.async.cg.shared.global [%0], [%1], 16;" :: "r"(d), "l"(s));
}
__device__ __forceinline__ void cp_commit() { asm volatile("cp.async.commit_group;" ::: "memory"); }
template<int N> __device__ __forceinline__ void cp_wait() {
    asm volatile("cp.async.wait_group %0;" :: "n"(N) : "memory");
}
__device__ __forceinline__ void ldsm4(uint32_t& r0, uint32_t& r1, uint32_t& r2, uint32_t& r3, uint32_t a) {
    asm volatile("ldmatrix.sync.aligned.m8n8.x4.shared.b16 {%0,%1,%2,%3}, [%4];"
        : "=r"(r0), "=r"(r1), "=r"(r2), "=r"(r3) : "r"(a));
}
__device__ __forceinline__ void mma16816(float* d, const uint32_t* a, const uint32_t* b) {
    asm volatile("mma.sync.aligned.m16n8k16.row.col.f32.bf16.bf16.f32 "
        "{%0,%1,%2,%3}, {%4,%5,%6,%7}, {%8,%9}, {%0,%1,%2,%3};"
        : "+f"(d[0]), "+f"(d[1]), "+f"(d[2]), "+f"(d[3])
        : "r"(a[0]), "r"(a[1]), "r"(a[2]), "r"(a[3]), "r"(b[0]), "r"(b[1]));
}
__device__ __forceinline__ float fsig(float x)  { return 1.0f / (1.0f + __expf(-x)); }
__device__ __forceinline__ float ftanh(float x) { return 2.0f / (1.0f + __expf(-2.0f * x)) - 1.0f; }

// per-mt-group barrier: 32 CTAs per group
__device__ __forceinline__ void gbar(int grp, unsigned& sense) {
    unsigned want = sense ^ 1u;
    __threadfence();
    __syncthreads();
    if (threadIdx.x == 0) {
        unsigned* cnt = &g_bcnt[grp * 32];
        unsigned* sns = &g_bsense[grp * 32];
        if (atomicAdd(cnt, 1u) == 31u) {
            *cnt = 0; __threadfence(); atomicExch(sns, want);
        } else {
            while (*(volatile unsigned*)sns != want) __nanosleep(32);
            __threadfence();
        }
    }
    __syncthreads();
    sense = want;
}

__device__ __forceinline__ void split8(const float* v, uint4& uh, uint4& ul) {
    uint32_t ph[4], pl[4];
    #pragma unroll
    for (int e = 0; e < 4; ++e) {
        __nv_bfloat16 b0 = __float2bfloat16(v[2*e]),   b1 = __float2bfloat16(v[2*e+1]);
        __nv_bfloat16 l0 = __float2bfloat16(v[2*e]   - __bfloat162float(b0));
        __nv_bfloat16 l1 = __float2bfloat16(v[2*e+1] - __bfloat162float(b1));
        ph[e] = (uint32_t)__bfloat16_as_ushort(b0) | ((uint32_t)__bfloat16_as_ushort(b1) << 16);
        pl[e] = (uint32_t)__bfloat16_as_ushort(l0) | ((uint32_t)__bfloat16_as_ushort(l1) << 16);
    }
    uh = make_uint4(ph[0], ph[1], ph[2], ph[3]);
    ul = make_uint4(pl[0], pl[1], pl[2], pl[3]);
}

// one fused chunk: A 64x64 (hi+lo) + optional W1 32(n')x64 + optional W2 32(n')x64
// stage layout: A_hi 0 | A_lo 8K | W1_hi 16K | W1_lo 20K | W2_hi 24K | W2_lo 28K
__device__ __forceinline__ void copy_fused(uint32_t sb, int tid,
    const uint4* ah, const uint4* al, int astr,
    const uint4* w1h, const uint4* w1l,
    const uint4* w2h, const uint4* w2l, bool dw1, bool dw2)
{
    #pragma unroll
    for (int i = 0; i < 2; ++i) {
        int idx = i * 256 + tid;
        int r = idx >> 3, g = idx & 7;
        uint32_t d = sb + (uint32_t)r * 128 + (uint32_t)((g ^ (r & 7)) << 4);
        cp16(d,        ah + (size_t)r * astr + g);
        cp16(d + 8192, al + (size_t)r * astr + g);
    }
    {
        int r = tid >> 3, g = tid & 7;   // 32 n'-rows x 8 gran
        uint32_t dw = (uint32_t)r * 128 + (uint32_t)((g ^ (r & 7)) << 4);
        if (dw1) {
            cp16(sb + 16384u + dw, w1h + (size_t)r * 48 + g);
            cp16(sb + 20480u + dw, w1l + (size_t)r * 48 + g);
        }
        if (dw2) {
            cp16(sb + 24576u + dw, w2h + (size_t)r * 64 + g);
            cp16(sb + 28672u + dw, w2l + (size_t)r * 64 + g);
        }
    }
    cp_commit();
}

// consume one fused chunk: A frags loaded once, MMA'd against W1 (acc1) and W2 (acc2)
__device__ __forceinline__ void compute_fused(uint32_t sb, int lane, int wr, int wc, int kh,
    bool dw1, bool dw2, float (&acc1)[2][2][4], float (&acc2)[2][2][4])
{
    const int t_ = lane >> 3, l7 = lane & 7;
    const int atq = t_ >> 1, btq = t_ & 1;
    const int arow0 = wr + ((t_ & 1) << 3) + l7;
    const int arow1 = arow0 + 16;
    const int brow  = wc + ((t_ >> 1) << 3) + l7;
    const int kg0 = kh * 4;

    #pragma unroll
    for (int kb = 0; kb < 2; ++kb) {
        const int kg = kg0 + kb * 2;
        uint32_t ah[2][4], al[2][4], b1h[4], b1l[4], b2h[4], b2l[4];
        uint32_t ad0 = sb + (uint32_t)arow0 * 128 + (uint32_t)(((kg + atq) ^ (arow0 & 7)) << 4);
        ldsm4(ah[0][0], ah[0][1], ah[0][2], ah[0][3], ad0);
        ldsm4(al[0][0], al[0][1], al[0][2], al[0][3], ad0 + 8192);
        uint32_t ad1 = sb + (uint32_t)arow1 * 128 + (uint32_t)(((kg + atq) ^ (arow1 & 7)) << 4);
        ldsm4(ah[1][0], ah[1][1], ah[1][2], ah[1][3], ad1);
        ldsm4(al[1][0], al[1][1], al[1][2], al[1][3], ad1 + 8192);
        uint32_t boff = (uint32_t)brow * 128 + (uint32_t)(((kg + btq) ^ (brow & 7)) << 4);
        if (dw1) {
            ldsm4(b1h[0], b1h[1], b1h[2], b1h[3], sb + 16384u + boff);
            ldsm4(b1l[0], b1l[1], b1l[2], b1l[3], sb + 20480u + boff);
        }
        if (dw2) {
            ldsm4(b2h[0], b2h[1], b2h[2], b2h[3], sb + 24576u + boff);
            ldsm4(b2l[0], b2l[1], b2l[2], b2l[3], sb + 28672u + boff);
        }
        if (dw1) {
            #pragma unroll
            for (int mb = 0; mb < 2; ++mb)
                #pragma unroll
                for (int nb = 0; nb < 2; ++nb) {
                    mma16816(acc1[mb][nb], ah[mb], &b1h[nb * 2]);
                    mma16816(acc1[mb][nb], ah[mb], &b1l[nb * 2]);
                    mma16816(acc1[mb][nb], al[mb], &b1h[nb * 2]);
                }
        }
        if (dw2) {
            #pragma unroll
            for (int mb = 0; mb < 2; ++mb)
                #pragma unroll
                for (int nb = 0; nb < 2; ++nb) {
                    mma16816(acc2[mb][nb], ah[mb], &b2h[nb * 2]);
                    mma16816(acc2[mb][nb], ah[mb], &b2l[nb * 2]);
                    mma16816(acc2[mb][nb], al[mb], &b2h[nb * 2]);
                }
        }
    }
}

// sG aliases stage 0 (dead by epilogue time). 2 K-planes x 64 rows x 40 floats.
__device__ __forceinline__ void epilogue(float (&acc)[2][2][4], float* sG, const float* sb,
    float (&cst)[2], uint32_t* dh, uint32_t* dl, float* h2fb,
    int tid, int lane, int wr, int wc, int kh, int jt)
{
    float* sp = sG + kh * 2560;
    #pragma unroll
    for (int mb = 0; mb < 2; ++mb)
        #pragma unroll
        for (int nb = 0; nb < 2; ++nb) {
            int r0 = wr + mb * 16 + (lane >> 2);
            int cc = wc + nb * 8 + (lane & 3) * 2;
            *(float2*)&sp[r0 * 40 + cc]       = make_float2(acc[mb][nb][0], acc[mb][nb][1]);
            *(float2*)&sp[(r0 + 8) * 40 + cc] = make_float2(acc[mb][nb][2], acc[mb][nb][3]);
        }
    __syncthreads();
    const int r = tid >> 2, ju = (tid & 3) * 2;
    float hv[2];
    #pragma unroll
    for (int u = 0; u < 2; ++u) {
        int jj = ju + u;
        float gf = sG[r * 40 + jj]      + sG[2560 + r * 40 + jj]      + sb[jj];
        float gi = sG[r * 40 + 8 + jj]  + sG[2560 + r * 40 + 8 + jj]  + sb[8 + jj];
        float gg = sG[r * 40 + 16 + jj] + sG[2560 + r * 40 + 16 + jj] + sb[16 + jj];
        float go = sG[r * 40 + 24 + jj] + sG[2560 + r * 40 + 24 + jj] + sb[24 + jj];
        float f = fsig(gf), i = fsig(gi), g = ftanh(gg), o = fsig(go);
        float c = f * cst[u] + i * g;
        cst[u] = c;
        hv[u] = o * ftanh(c);
    }
    __nv_bfloat16 b0 = __float2bfloat16(hv[0]), b1 = __float2bfloat16(hv[1]);
    __nv_bfloat16 l0 = __float2bfloat16(hv[0] - __bfloat162float(b0));
    __nv_bfloat16 l1 = __float2bfloat16(hv[1] - __bfloat162float(b1));
    dh[r * 128 + (ju >> 1)] = (uint32_t)__bfloat16_as_ushort(b0) | ((uint32_t)__bfloat16_as_ushort(b1) << 16);
    dl[r * 128 + (ju >> 1)] = (uint32_t)__bfloat16_as_ushort(l0) | ((uint32_t)__bfloat16_as_ushort(l1) << 16);
    if (h2fb) {
        h2fb[(size_t)r * 256 + jt * 8 + ju]     = hv[0];
        h2fb[(size_t)r * 256 + jt * 8 + ju + 1] = hv[1];
    }
    __syncthreads();
}

__global__ void __launch_bounds__(NTH, 2)
lstm_mma_kernel(const float* __restrict__ b1, const float* __restrict__ b2,
                const float* __restrict__ Wout, const float* __restrict__ bout,
                float* __restrict__ out)
{
    extern __shared__ uint4 dsm[];
    __shared__ float s_b1[32], s_b2[32];

    const int tid = threadIdx.x, cta = blockIdx.x;
    const int warp = tid >> 5, lane = tid & 31;
    const int mt = cta >> 5, jt = cta & 31;
    const int kh = warp & 1;                       // 2(M:32) x 2(N:16) x 2(K-split)
    const int wr = ((warp >> 1) & 1) * 32, wc = (warp >> 2) * 16;
    uint32_t base32 = (sm32(dsm) + 1023u) & ~1023u;
    float* sG = (float*)((char*)dsm + (base32 - sm32(dsm)));   // alias stage 0

    if (tid < 32) {
        int gate = tid >> 3, u = tid & 7;
        s_b1[tid] = b1[gate * H_ + jt * 8 + u];
        s_b2[tid] = b2[gate * H_ + jt * 8 + u];
    }
    {   // zero this group's h rows
        int i = jt * NTH + tid;
        if (i < 4096) {
            int buf = i >> 11, rr = (i >> 5) & 63, g = i & 31;
            size_t idx = (size_t)buf * 16384 + (size_t)(mt * 64 + rr) * 32 + g;
            uint4 z = make_uint4(0, 0, 0, 0);
            g_h1_hi[idx] = z; g_h1_lo[idx] = z; g_h2_hi[idx] = z; g_h2_lo[idx] = z;
        }
    }
    unsigned sense = 0;
    gbar(mt, sense);                               // group barrier #1

    float c1[2] = {0.f, 0.f}, c2[2] = {0.f, 0.f};

    const uint4* w1h = g_w1_hi + (size_t)(jt * 32) * 48;
    const uint4* w1l = g_w1_lo + (size_t)(jt * 32) * 48;
    const uint4* w2h = g_w2_hi + (size_t)(jt * 32) * 64;
    const uint4* w2l = g_w2_lo + (size_t)(jt * 32) * 64;

    for (int p = 0; p < 1025; ++p) {
        const bool do1 = p < 1024, do2 = p > 0;
        float acc1[2][2][4], acc2[2][2][4];
        #pragma unroll
        for (int mb = 0; mb < 2; ++mb)
            #pragma unroll
            for (int nb = 0; nb < 2; ++nb)
                #pragma unroll
                for (int e = 0; e < 4; ++e) { acc1[mb][nb][e] = 0.f; acc2[mb][nb][e] = 0.f; }

        const int rb1 = (p - 1) & 1, rb2 = p & 1;
        const uint4* h1r_h = g_h1_hi + ((size_t)rb1 * 512 + mt * 64) * 32;
        const uint4* h1r_l = g_h1_lo + ((size_t)rb1 * 512 + mt * 64) * 32;
        const uint4* h2r_h = g_h2_hi + ((size_t)rb2 * 512 + mt * 64) * 32;
        const uint4* h2r_l = g_h2_lo + ((size_t)rb2 * 512 + mt * 64) * 32;
        const int px = do1 ? p : 0;
        const uint4* xh = g_x_hi + ((size_t)px * 512 + mt * 64) * 16;
        const uint4* xl = g_x_lo + ((size_t)px * 512 + mt * 64) * 16;

        // fused chunk map: c<2 -> x(p) [W1]; c<6 -> h1(p-1) [W1+W2]; c<10 -> h2(p-2) [W2]
        auto ahp = [&](int c) { return c < 2 ? xh + c * 8 : c < 6 ? h1r_h + (c - 2) * 8 : h2r_h + (c - 6) * 8; };
        auto alp = [&](int c) { return c < 2 ? xl + c * 8 : c < 6 ? h1r_l + (c - 2) * 8 : h2r_l + (c - 6) * 8; };
        auto ast = [&](int c) { return c < 2 ? 16 : 32; };

        const int clo = do1 ? 0 : 2;
        const int chi = do2 ? 10 : 6;

        #pragma unroll
        for (int q = 0; q < 2; ++q) {              // prologue: chunks clo, clo+1
            int c = clo + q;
            copy_fused(base32 + (c % 3) * STG, tid, ahp(c), alp(c), ast(c),
                       w1h + c * 8, w1l + c * 8, w2h + (c - 2) * 8, w2l + (c - 2) * 8,
                       do1 && c < 6, do2 && c >= 2);
        }
        for (int c = clo; c < chi; ++c) {
            if (c < chi - 1) cp_wait<1>(); else cp_wait<0>();
            __syncthreads();
            if (c + 2 < chi) {
                int cc = c + 2;
                copy_fused(base32 + (cc % 3) * STG, tid, ahp(cc), alp(cc), ast(cc),
                           w1h + cc * 8, w1l + cc * 8, w2h + (cc - 2) * 8, w2l + (cc - 2) * 8,
                           do1 && cc < 6, do2);
            }
            compute_fused(base32 + (c % 3) * STG, lane, wr, wc, kh,
                          do1 && c < 6, do2 && c >= 2, acc1, acc2);
        }
        __syncthreads();                           // stages dead; sG (stage 0) reusable

        if (do1) {
            const int wb = p & 1;
            uint32_t* dh = (uint32_t*)(g_h1_hi + ((size_t)wb * 512 + mt * 64) * 32) + jt * 4;
            uint32_t* dl = (uint32_t*)(g_h1_lo + ((size_t)wb * 512 + mt * 64) * 32) + jt * 4;
            epilogue(acc1, sG, s_b1, c1, dh, dl, (float*)0, tid, lane, wr, wc, kh, jt);
        }
        if (do2) {
            const int wb = (p - 1) & 1;
            uint32_t* dh = (uint32_t*)(g_h2_hi + ((size_t)wb * 512 + mt * 64) * 32) + jt * 4;
            uint32_t* dl = (uint32_t*)(g_h2_lo + ((size_t)wb * 512 + mt * 64) * 32) + jt * 4;
            float* hb = (p == 1024) ? g_h2f + (size_t)(mt * 64) * 256 : (float*)0;
            epilogue(acc2, sG, s_b2, c2, dh, dl, hb, tid, lane, wr, wc, kh, jt);
        }
        gbar(mt, sense);                           // group total 1026 barriers (even)
    }

    if (jt == 0 && tid < 64) {
        int row = mt * 64 + tid;
        float s = 0.f;
        #pragma unroll 8
        for (int k = 0; k < H_; ++k) s += g_h2f[(size_t)row * H_ + k] * Wout[k];
        out[row] = s + bout[0];
    }
}

// ---------------- prep: split fp32 -> bf16 hi/lo planes ----------------
__global__ void prep_x_kernel(const float* __restrict__ x) {
    long gid = (long)blockIdx.x * 256 + threadIdx.x;
    int g = (int)(gid & 15);
    int b = (int)((gid >> 4) & 511);
    int t = (int)(gid >> 13);
    const float* src = x + ((size_t)b * 1024 + t) * 128 + g * 8;
    float4 f0 = *(const float4*)src, f1 = *(const float4*)(src + 4);
    float v[8] = {f0.x, f0.y, f0.z, f0.w, f1.x, f1.y, f1.z, f1.w};
    uint4 uh, ul;
    split8(v, uh, ul);
    size_t di = ((size_t)t * 512 + b) * 16 + g;
    g_x_hi[di] = uh; g_x_lo[di] = ul;
}

template<int K, int L>
__global__ void prep_w_kernel(const float* __restrict__ W) {
    uint4* dhi = (L == 1) ? g_w1_hi : g_w2_hi;
    uint4* dlo = (L == 1) ? g_w1_lo : g_w2_lo;
    int gid = blockIdx.x * 256 + threadIdx.x;
    int kg = gid % (K / 8);
    int np = gid / (K / 8);                        // n' = jt*32 + gate*8 + u
    int jt = np >> 5, gate = (np >> 3) & 3, u = np & 7;
    int col = gate * 256 + jt * 8 + u;
    float v[8];
    #pragma unroll
    for (int e = 0; e < 8; ++e) v[e] = W[(size_t)(kg * 8 + e) * 1024 + col];
    uint4 uh, ul;
    split8(v, uh, ul);
    dhi[(size_t)np * (K / 8) + kg] = uh;
    dlo[(size_t)np * (K / 8) + kg] = ul;
}

extern "C" void kernel_launch(void* const* d_in, const int* in_sizes, int n_in,
                              void* d_out, int out_size)
{
    (void)in_sizes; (void)n_in; (void)out_size;
    const float* x    = (const float*)d_in[0];
    const float* W1   = (const float*)d_in[1];
    const float* b1   = (const float*)d_in[2];
    const float* W2   = (const float*)d_in[3];
    const float* b2   = (const float*)d_in[4];
    const float* Wout = (const float*)d_in[5];
    const float* bout = (const float*)d_in[6];
    cudaFuncSetAttribute(lstm_mma_kernel, cudaFuncAttributeMaxDynamicSharedMemorySize, SMEM_DYN);
    prep_x_kernel<<<32768, 256>>>(x);
    prep_w_kernel<384, 1><<<192, 256>>>(W1);
    prep_w_kernel<512, 2><<<256, 256>>>(W2);
    lstm_mma_kernel<<<NCTA, NTH, SMEM_DYN>>>(b1, b2, Wout, bout, (float*)d_out);
}

// round 15
// speedup vs baseline: 1.3815x; 1.3815x over previous
#include <cuda_runtime.h>
#include <cuda_fp16.h>
#include <cstdint>

#define B_   512
#define T_   1024
#define H_   256
#define NCTA 256
#define NTH  256
#define STG  16384
#define SG_BYTES (2*64*40*4)
#define SMEM_DYN (1024 + 3*STG + SG_BYTES)

__device__ uint4 g_x_h[8388608];                 // [t][512][16 gran] fp16
__device__ uint4 g_w1_h[49152], g_w1_l[49152];   // [n'=1024][48 gran] fp16 hi/lo
__device__ uint4 g_w2_h[65536], g_w2_l[65536];   // [n'=1024][64 gran]
__device__ uint4 g_h1_h[32768];                  // [buf2][512][32 gran] fp16
__device__ uint4 g_h2_h[32768];
__device__ float g_h2f[B_ * H_];
__device__ unsigned g_bcnt[8 * 32];
__device__ unsigned g_bsense[8 * 32];

__device__ __forceinline__ uint32_t sm32(const void* p) {
    uint32_t a;
    asm("{ .reg .u64 t; cvta.to.shared.u64 t, %1; cvt.u32.u64 %0, t; }" : "=r"(a) : "l"(p));
    return a;
}
__device__ __forceinline__ void cp16(uint32_t d, const void* s) {
    asm volatile("cp.async.cg.shared.global [%0], [%1], 16;" :: "r"(d), "l"(s));
}
__device__ __forceinline__ void cp_commit() { asm volatile("cp.async.commit_group;" ::: "memory"); }
template<int N> __device__ __forceinline__ void cp_wait() {
    asm volatile("cp.async.wait_group %0;" :: "n"(N) : "memory");
}
__device__ __forceinline__ void ldsm4(uint32_t& r0, uint32_t& r1, uint32_t& r2, uint32_t& r3, uint32_t a) {
    asm volatile("ldmatrix.sync.aligned.m8n8.x4.shared.b16 {%0,%1,%2,%3}, [%4];"
        : "=r"(r0), "=r"(r1), "=r"(r2), "=r"(r3) : "r"(a));
}
__device__ __forceinline__ void mma16816(float* d, const uint32_t* a, const uint32_t* b) {
    asm volatile("mma.sync.aligned.m16n8k16.row.col.f32.f16.f16.f32 "
        "{%0,%1,%2,%3}, {%4,%5,%6,%7}, {%8,%9}, {%0,%1,%2,%3};"
        : "+f"(d[0]), "+f"(d[1]), "+f"(d[2]), "+f"(d[3])
        : "r"(a[0]), "r"(a[1]), "r"(a[2]), "r"(a[3]), "r"(b[0]), "r"(b[1]));
}
__device__ __forceinline__ float fsig(float x)  { return 1.0f / (1.0f + __expf(-x)); }
__device__ __forceinline__ float ftanh(float x) { return 2.0f / (1.0f + __expf(-2.0f * x)) - 1.0f; }

// per-mt-group barrier: 32 CTAs per group
__device__ __forceinline__ void gbar(int grp, unsigned& sense) {
    unsigned want = sense ^ 1u;
    __threadfence();
    __syncthreads();
    if (threadIdx.x == 0) {
        unsigned* cnt = &g_bcnt[grp * 32];
        unsigned* sns = &g_bsense[grp * 32];
        if (atomicAdd(cnt, 1u) == 31u) {
            *cnt = 0; __threadfence(); atomicExch(sns, want);
        } else {
            while (*(volatile unsigned*)sns != want) __nanosleep(32);
            __threadfence();
        }
    }
    __syncthreads();
    sense = want;
}

// pack 8 floats -> fp16x8 (one uint4)
__device__ __forceinline__ uint4 packh8(const float* v) {
    uint32_t p[4];
    #pragma unroll
    for (int e = 0; e < 4; ++e) {
        __half h0 = __float2half(v[2*e]), h1 = __float2half(v[2*e+1]);
        p[e] = (uint32_t)__half_as_ushort(h0) | ((uint32_t)__half_as_ushort(h1) << 16);
    }
    return make_uint4(p[0], p[1], p[2], p[3]);
}
// split 8 floats -> fp16 hi + fp16 lo planes
__device__ __forceinline__ void splith8(const float* v, uint4& uh, uint4& ul) {
    uint32_t ph[4], pl[4];
    #pragma unroll
    for (int e = 0; e < 4; ++e) {
        __half h0 = __float2half(v[2*e]),   h1 = __float2half(v[2*e+1]);
        __half l0 = __float2half(v[2*e]   - __half2float(h0));
        __half l1 = __float2half(v[2*e+1] - __half2float(h1));
        ph[e] = (uint32_t)__half_as_ushort(h0) | ((uint32_t)__half_as_ushort(h1) << 16);
        pl[e] = (uint32_t)__half_as_ushort(l0) | ((uint32_t)__half_as_ushort(l1) << 16);
    }
    uh = make_uint4(ph[0], ph[1], ph[2], ph[3]);
    ul = make_uint4(pl[0], pl[1], pl[2], pl[3]);
}

// copy one 64x64 A tile (fp16, hi only) + 32(n')x64 W tile (hi+lo) into stage sb, swizzled
// stage layout: A 0..8K | W_hi 8K..12K | W_lo 12K..16K
__device__ __forceinline__ void copy_chunk(uint32_t sb, int tid,
    const uint4* ah, int astr,
    const uint4* wh, const uint4* wl, int wstr)
{
    #pragma unroll
    for (int i = 0; i < 2; ++i) {
        int idx = i * 256 + tid;
        int r = idx >> 3, g = idx & 7;
        uint32_t d = sb + (uint32_t)r * 128 + (uint32_t)((g ^ (r & 7)) << 4);
        cp16(d, ah + (size_t)r * astr + g);
    }
    {
        int r = tid >> 3, g = tid & 7;   // 32 n'-rows x 8 gran
        uint32_t d = sb + 8192u + (uint32_t)r * 128 + (uint32_t)((g ^ (r & 7)) << 4);
        cp16(d,        wh + (size_t)r * wstr + g);
        cp16(d + 4096, wl + (size_t)r * wstr + g);
    }
    cp_commit();
}

// one k16-block fragment set: A 32x16 (hi), B 16x16 (hi+lo)
struct FragK {
    uint32_t ah[2][4], bh[4], bl[4];
};

__device__ __forceinline__ void load_khalf(uint32_t sb, int lane, int wr, int wc,
                                           int kg, FragK& f)
{
    const int t_ = lane >> 3, l7 = lane & 7;
    const int atq = t_ >> 1, btq = t_ & 1;
    const int arow0 = wr + ((t_ & 1) << 3) + l7;
    const int arow1 = arow0 + 16;
    const int brow  = wc + ((t_ >> 1) << 3) + l7;
    uint32_t ad0 = sb + (uint32_t)arow0 * 128 + (uint32_t)(((kg + atq) ^ (arow0 & 7)) << 4);
    ldsm4(f.ah[0][0], f.ah[0][1], f.ah[0][2], f.ah[0][3], ad0);
    uint32_t ad1 = sb + (uint32_t)arow1 * 128 + (uint32_t)(((kg + atq) ^ (arow1 & 7)) << 4);
    ldsm4(f.ah[1][0], f.ah[1][1], f.ah[1][2], f.ah[1][3], ad1);
    uint32_t bd = sb + 8192u + (uint32_t)brow * 128 + (uint32_t)(((kg + btq) ^ (brow & 7)) << 4);
    ldsm4(f.bh[0], f.bh[1], f.bh[2], f.bh[3], bd);
    ldsm4(f.bl[0], f.bl[1], f.bl[2], f.bl[3], bd + 4096);
}

__device__ __forceinline__ void mma_khalf(const FragK& f, float (&acc)[2][2][4]) {
    #pragma unroll
    for (int mb = 0; mb < 2; ++mb)
        #pragma unroll
        for (int nb = 0; nb < 2; ++nb) {
            mma16816(acc[mb][nb], f.ah[mb], &f.bh[nb * 2]);
            mma16816(acc[mb][nb], f.ah[mb], &f.bl[nb * 2]);
        }
}

__device__ __forceinline__ void compute_chunk(uint32_t sb, int lane, int wr, int wc, int kh,
                                              float (&acc)[2][2][4])
{
    const int kg0 = kh * 4;
    FragK fA, fB;
    load_khalf(sb, lane, wr, wc, kg0, fA);
    load_khalf(sb, lane, wr, wc, kg0 + 2, fB);
    mma_khalf(fA, acc);
    mma_khalf(fB, acc);
}

#define SRC(c) \
    const uint4* sah = ((c) < N0) ? a0h + (c)*8 : a1h + ((c)-N0)*8; \
    int sstr = ((c) < N0) ? S0 : S1;

template<int NC, int N0, int S0, int S1>
__device__ __forceinline__ void gemm_prol(uint32_t base32, int tid,
    const uint4* a0h, const uint4* a1h,
    const uint4* wh, const uint4* wl, int wstr)
{
    #pragma unroll
    for (int c = 0; c < 2; ++c) {
        SRC(c);
        copy_chunk(base32 + c * STG, tid, sah, sstr, wh + c * 8, wl + c * 8, wstr);
    }
}

// 3 stages, copy-lead 2, single sync per chunk (copy before compute)
template<int NC, int N0, int S0, int S1>
__device__ __forceinline__ void gemm_main(uint32_t base32, int tid, int lane,
    int wr, int wc, int kh,
    const uint4* a0h, const uint4* a1h,
    const uint4* wh, const uint4* wl, int wstr, float (&acc)[2][2][4])
{
    #pragma unroll
    for (int c = 0; c < NC; ++c) {
        if (c < NC - 1) cp_wait<1>(); else cp_wait<0>();
        __syncthreads();
        if (c + 2 < NC) {
            SRC(c + 2);
            int s = (c + 2) % 3;
            copy_chunk(base32 + s * STG, tid, sah, sstr,
                       wh + (c + 2) * 8, wl + (c + 2) * 8, wstr);
        }
        compute_chunk(base32 + (c % 3) * STG, lane, wr, wc, kh, acc);
    }
    __syncthreads();   // all warps done before stages are recycled
}

// dh: uint32_t* pre-offset to (buf, row0=mt*64, u32-col jt*4); row stride 128 u32
__device__ __forceinline__ void epilogue(float (&acc)[2][2][4], float* sG, const float* sb,
    float (&cst)[2], uint32_t* dh, float* h2fb,
    int tid, int lane, int wr, int wc, int kh, int jt)
{
    float* sp = sG + kh * 2560;
    #pragma unroll
    for (int mb = 0; mb < 2; ++mb)
        #pragma unroll
        for (int nb = 0; nb < 2; ++nb) {
            int r0 = wr + mb * 16 + (lane >> 2);
            int cc = wc + nb * 8 + (lane & 3) * 2;
            *(float2*)&sp[r0 * 40 + cc]       = make_float2(acc[mb][nb][0], acc[mb][nb][1]);
            *(float2*)&sp[(r0 + 8) * 40 + cc] = make_float2(acc[mb][nb][2], acc[mb][nb][3]);
        }
    __syncthreads();
    const int r = tid >> 2, ju = (tid & 3) * 2;
    float hv[2];
    #pragma unroll
    for (int u = 0; u < 2; ++u) {
        int jj = ju + u;
        float gf = sG[r * 40 + jj]      + sG[2560 + r * 40 + jj]      + sb[jj];
        float gi = sG[r * 40 + 8 + jj]  + sG[2560 + r * 40 + 8 + jj]  + sb[8 + jj];
        float gg = sG[r * 40 + 16 + jj] + sG[2560 + r * 40 + 16 + jj] + sb[16 + jj];
        float go = sG[r * 40 + 24 + jj] + sG[2560 + r * 40 + 24 + jj] + sb[24 + jj];
        float f = fsig(gf), i = fsig(gi), g = ftanh(gg), o = fsig(go);
        float c = f * cst[u] + i * g;
        cst[u] = c;
        hv[u] = o * ftanh(c);
    }
    __half a0 = __float2half(hv[0]), a1 = __float2half(hv[1]);
    dh[r * 128 + (ju >> 1)] = (uint32_t)__half_as_ushort(a0) | ((uint32_t)__half_as_ushort(a1) << 16);
    if (h2fb) {
        h2fb[(size_t)r * 256 + jt * 8 + ju]     = hv[0];
        h2fb[(size_t)r * 256 + jt * 8 + ju + 1] = hv[1];
    }
    __syncthreads();
}

__global__ void __launch_bounds__(NTH, 2)
lstm_mma_kernel(const float* __restrict__ b1, const float* __restrict__ b2,
                const float* __restrict__ Wout, const float* __restrict__ bout,
                float* __restrict__ out)
{
    extern __shared__ uint4 dsm[];
    __shared__ float s_b1[32], s_b2[32];

    const int tid = threadIdx.x, cta = blockIdx.x;
    const int warp = tid >> 5, lane = tid & 31;
    const int mt = cta >> 5, jt = cta & 31;
    const int kh = warp & 1;                       // 2(M:32) x 2(N:16) x 2(K-split)
    const int wr = ((warp >> 1) & 1) * 32, wc = (warp >> 2) * 16;
    uint32_t base32 = (sm32(dsm) + 1023u) & ~1023u;
    float* sG = (float*)((char*)dsm + ((base32 - sm32(dsm)) + 3 * STG));

    if (tid < 32) {
        int gate = tid >> 3, u = tid & 7;
        s_b1[tid] = b1[gate * H_ + jt * 8 + u];
        s_b2[tid] = b2[gate * H_ + jt * 8 + u];
    }
    {   // zero this group's h rows
        int i = jt * NTH + tid;
        if (i < 4096) {
            int buf = i >> 11, rr = (i >> 5) & 63, g = i & 31;
            size_t idx = (size_t)buf * 16384 + (size_t)(mt * 64 + rr) * 32 + g;
            uint4 z = make_uint4(0, 0, 0, 0);
            g_h1_h[idx] = z; g_h2_h[idx] = z;
        }
    }
    unsigned sense = 0;
    gbar(mt, sense);                               // group barrier #1

    float c1[2] = {0.f, 0.f}, c2[2] = {0.f, 0.f};

    const uint4* w1h = g_w1_h + (size_t)(jt * 32) * 48;
    const uint4* w1l = g_w1_l + (size_t)(jt * 32) * 48;
    const uint4* w2h = g_w2_h + (size_t)(jt * 32) * 64;
    const uint4* w2l = g_w2_l + (size_t)(jt * 32) * 64;

    for (int p = 0; p < 1025; ++p) {
        const bool do1 = p < 1024, do2 = p > 0;
        float acc1[2][2][4], acc2[2][2][4];

        const int rb1 = (p - 1) & 1;               // h1(p-1) buffer
        const int rb2 = p & 1;                     // h2(p-2) buffer
        const uint4* h1r = g_h1_h + ((size_t)rb1 * 512 + mt * 64) * 32;
        const uint4* h2r = g_h2_h + ((size_t)rb2 * 512 + mt * 64) * 32;

        if (do1) {
            const uint4* xh = g_x_h + ((size_t)p * 512 + mt * 64) * 16;
            #pragma unroll
            for (int mb = 0; mb < 2; ++mb)
                #pragma unroll
                for (int nb = 0; nb < 2; ++nb)
                    #pragma unroll
                    for (int e = 0; e < 4; ++e) acc1[mb][nb][e] = 0.f;
            gemm_prol<6,2,16,32>(base32, tid, xh, h1r, w1h, w1l, 48);
            gemm_main<6,2,16,32>(base32, tid, lane, wr, wc, kh, xh, h1r,
                                 w1h, w1l, 48, acc1);
        }
        if (do2) {
            #pragma unroll
            for (int mb = 0; mb < 2; ++mb)
                #pragma unroll
                for (int nb = 0; nb < 2; ++nb)
                    #pragma unroll
                    for (int e = 0; e < 4; ++e) acc2[mb][nb][e] = 0.f;
            gemm_prol<8,4,32,32>(base32, tid, h1r, h2r, w2h, w2l, 64);
        }
        if (do1) {
            const int wb = p & 1;
            uint32_t* dh = (uint32_t*)(g_h1_h + ((size_t)wb * 512 + mt * 64) * 32) + jt * 4;
            epilogue(acc1, sG, s_b1, c1, dh, (float*)0, tid, lane, wr, wc, kh, jt);
        }
        if (do2) {
            gemm_main<8,4,32,32>(base32, tid, lane, wr, wc, kh, h1r, h2r,
                                 w2h, w2l, 64, acc2);
            const int wb = (p - 1) & 1;
            uint32_t* dh = (uint32_t*)(g_h2_h + ((size_t)wb * 512 + mt * 64) * 32) + jt * 4;
            float* hb = (p == 1024) ? g_h2f + (size_t)(mt * 64) * 256 : (float*)0;
            epilogue(acc2, sG, s_b2, c2, dh, hb, tid, lane, wr, wc, kh, jt);
        }
        gbar(mt, sense);                           // group total 1026 barriers (even)
    }

    if (jt == 0 && tid < 64) {
        int row = mt * 64 + tid;
        float s = 0.f;
        #pragma unroll 8
        for (int k = 0; k < H_; ++k) s += g_h2f[(size_t)row * H_ + k] * Wout[k];
        out[row] = s + bout[0];
    }
}

// ---------------- prep: fp16 planes ----------------
__global__ void prep_x_kernel(const float* __restrict__ x) {
    long gid = (long)blockIdx.x * 256 + threadIdx.x;
    int g = (int)(gid & 15);
    int b = (int)((gid >> 4) & 511);
    int t = (int)(gid >> 13);
    const float* src = x + ((size_t)b * 1024 + t) * 128 + g * 8;
    float4 f0 = *(const float4*)src, f1 = *(const float4*)(src + 4);
    float v[8] = {f0.x, f0.y, f0.z, f0.w, f1.x, f1.y, f1.z, f1.w};
    size_t di = ((size_t)t * 512 + b) * 16 + g;
    g_x_h[di] = packh8(v);
}

template<int K, int L>
__global__ void prep_w_kernel(const float* __restrict__ W) {
    uint4* dhi = (L == 1) ? g_w1_h : g_w2_h;
    uint4* dlo = (L == 1) ? g_w1_l : g_w2_l;
    int gid = blockIdx.x * 256 + threadIdx.x;
    int kg = gid % (K / 8);
    int np = gid / (K / 8);                        // n' = jt*32 + gate*8 + u
    int jt = np >> 5, gate = (np >> 3) & 3, u = np & 7;
    int col = gate * 256 + jt * 8 + u;
    float v[8];
    #pragma unroll
    for (int e = 0; e < 8; ++e) v[e] = W[(size_t)(kg * 8 + e) * 1024 + col];
    uint4 uh, ul;
    splith8(v, uh, ul);
    dhi[(size_t)np * (K / 8) + kg] = uh;
    dlo[(size_t)np * (K / 8) + kg] = ul;
}

extern "C" void kernel_launch(void* const* d_in, const int* in_sizes, int n_in,
                              void* d_out, int out_size)
{
    (void)in_sizes; (void)n_in; (void)out_size;
    const float* x    = (const float*)d_in[0];
    const float* W1   = (const float*)d_in[1];
    const float* b1   = (const float*)d_in[2];
    const float* W2   = (const float*)d_in[3];
    const float* b2   = (const float*)d_in[4];
    const float* Wout = (const float*)d_in[5];
    const float* bout = (const float*)d_in[6];
    cudaFuncSetAttribute(lstm_mma_kernel, cudaFuncAttributeMaxDynamicSharedMemorySize, SMEM_DYN);
    prep_x_kernel<<<32768, 256>>>(x);
    prep_w_kernel<384, 1><<<192, 256>>>(W1);
    prep_w_kernel<512, 2><<<256, 256>>>(W2);
    lstm_mma_kernel<<<NCTA, NTH, SMEM_DYN>>>(b1, b2, Wout, bout, (float*)d_out);
}

// round 16
// speedup vs baseline: 1.6563x; 1.1990x over previous
#include <cuda_runtime.h>
#include <cuda_fp16.h>
#include <cstdint>

#define B_   512
#define T_   1024
#define H_   256
#define NCTA 256
#define NTH  256
#define STG  8192
#define W1OFF 24576
#define W2OFF 49152
#define SGOFF 81920
#define SMEM_DYN (1024 + 102400)

__device__ uint4 g_x_h[8388608];             // [t][512][16 gran] fp16
__device__ uint4 g_w1_h[49152];              // [n'=1024][48 gran] fp16
__device__ uint4 g_w2_h[65536];              // [n'=1024][64 gran]
__device__ uint4 g_h1_h[32768];              // [buf2][512][32 gran] fp16
__device__ uint4 g_h2_h[32768];
__device__ float g_h2f[B_ * H_];
__device__ unsigned g_bcnt[8 * 32];
__device__ unsigned g_bsense[8 * 32];

__device__ __forceinline__ uint32_t sm32(const void* p) {
    uint32_t a;
    asm("{ .reg .u64 t; cvta.to.shared.u64 t, %1; cvt.u32.u64 %0, t; }" : "=r"(a) : "l"(p));
    return a;
}
__device__ __forceinline__ void cp16(uint32_t d, const void* s) {
    asm volatile("cp.async.cg.shared.global [%0], [%1], 16;" :: "r"(d), "l"(s));
}
__device__ __forceinline__ void cp_commit() { asm volatile("cp.async.commit_group;" ::: "memory"); }
template<int N> __device__ __forceinline__ void cp_wait() {
    asm volatile("cp.async.wait_group %0;" :: "n"(N) : "memory");
}
__device__ __forceinline__ void ldsm4(uint32_t& r0, uint32_t& r1, uint32_t& r2, uint32_t& r3, uint32_t a) {
    asm volatile("ldmatrix.sync.aligned.m8n8.x4.shared.b16 {%0,%1,%2,%3}, [%4];"
        : "=r"(r0), "=r"(r1), "=r"(r2), "=r"(r3) : "r"(a));
}
__device__ __forceinline__ void mma16816(float* d, const uint32_t* a, const uint32_t* b) {
    asm volatile("mma.sync.aligned.m16n8k16.row.col.f32.f16.f16.f32 "
        "{%0,%1,%2,%3}, {%4,%5,%6,%7}, {%8,%9}, {%0,%1,%2,%3};"
        : "+f"(d[0]), "+f"(d[1]), "+f"(d[2]), "+f"(d[3])
        : "r"(a[0]), "r"(a[1]), "r"(a[2]), "r"(a[3]), "r"(b[0]), "r"(b[1]));
}
__device__ __forceinline__ float fsig(float x)  { return 1.0f / (1.0f + __expf(-x)); }
__device__ __forceinline__ float ftanh(float x) { return 2.0f / (1.0f + __expf(-2.0f * x)) - 1.0f; }

// per-mt-group barrier: 32 CTAs per group
__device__ __forceinline__ void gbar(int grp, unsigned& sense) {
    unsigned want = sense ^ 1u;
    __threadfence();
    __syncthreads();
    if (threadIdx.x == 0) {
        unsigned* cnt = &g_bcnt[grp * 32];
        unsigned* sns = &g_bsense[grp * 32];
        if (atomicAdd(cnt, 1u) == 31u) {
            *cnt = 0; __threadfence(); atomicExch(sns, want);
        } else {
            while (*(volatile unsigned*)sns != want) __nanosleep(32);
            __threadfence();
        }
    }
    __syncthreads();
    sense = want;
}

// pack 8 floats -> fp16x8 (one uint4)
__device__ __forceinline__ uint4 packh8(const float* v) {
    uint32_t p[4];
    #pragma unroll
    for (int e = 0; e < 4; ++e) {
        __half h0 = __float2half(v[2*e]), h1 = __float2half(v[2*e+1]);
        p[e] = (uint32_t)__half_as_ushort(h0) | ((uint32_t)__half_as_ushort(h1) << 16);
    }
    return make_uint4(p[0], p[1], p[2], p[3]);
}

// copy one 64x64 A tile (fp16) into stage sb, swizzled (512 granules, 2 per thread)
__device__ __forceinline__ void copy_chunk(uint32_t sb, int tid, const uint4* ah, int astr)
{
    #pragma unroll
    for (int i = 0; i < 2; ++i) {
        int idx = i * 256 + tid;
        int r = idx >> 3, g = idx & 7;
        uint32_t d = sb + (uint32_t)r * 128 + (uint32_t)((g ^ (r & 7)) << 4);
        cp16(d, ah + (size_t)r * astr + g);
    }
    cp_commit();
}

// compute one chunk: A from stage sbA, W from persistent region wchunk
__device__ __forceinline__ void compute_chunk(uint32_t sbA, uint32_t wchunk,
    int lane, int wr, int wc, int kh, float (&acc)[2][2][4])
{
    const int t_ = lane >> 3, l7 = lane & 7;
    const int atq = t_ >> 1, btq = t_ & 1;
    const int arow0 = wr + ((t_ & 1) << 3) + l7;
    const int arow1 = arow0 + 16;
    const int brow  = wc + ((t_ >> 1) << 3) + l7;
    const int kg0 = kh * 4;

    #pragma unroll
    for (int kb = 0; kb < 2; ++kb) {
        const int kg = kg0 + kb * 2;
        uint32_t ah[2][4], bh[4];
        uint32_t ad0 = sbA + (uint32_t)arow0 * 128 + (uint32_t)(((kg + atq) ^ (arow0 & 7)) << 4);
        ldsm4(ah[0][0], ah[0][1], ah[0][2], ah[0][3], ad0);
        uint32_t ad1 = sbA + (uint32_t)arow1 * 128 + (uint32_t)(((kg + atq) ^ (arow1 & 7)) << 4);
        ldsm4(ah[1][0], ah[1][1], ah[1][2], ah[1][3], ad1);
        uint32_t bd = wchunk + (uint32_t)brow * 128 + (uint32_t)(((kg + btq) ^ (brow & 7)) << 4);
        ldsm4(bh[0], bh[1], bh[2], bh[3], bd);
        #pragma unroll
        for (int mb = 0; mb < 2; ++mb)
            #pragma unroll
            for (int nb = 0; nb < 2; ++nb)
                mma16816(acc[mb][nb], ah[mb], &bh[nb * 2]);
    }
}

#define SRC(c) \
    const uint4* sah = ((c) < N0) ? a0h + (c)*8 : a1h + ((c)-N0)*8; \
    int sstr = ((c) < N0) ? S0 : S1;

template<int NC, int N0, int S0, int S1>
__device__ __forceinline__ void gemm_prol(uint32_t base32, int tid,
    const uint4* a0h, const uint4* a1h)
{
    #pragma unroll
    for (int c = 0; c < 2; ++c) {
        SRC(c);
        copy_chunk(base32 + c * STG, tid, sah, sstr);
    }
}

// 3 A-stages, copy-lead 2, single sync per chunk; W read from persistent region
template<int NC, int N0, int S0, int S1>
__device__ __forceinline__ void gemm_main(uint32_t base32, uint32_t wbase, int tid, int lane,
    int wr, int wc, int kh,
    const uint4* a0h, const uint4* a1h, float (&acc)[2][2][4])
{
    #pragma unroll
    for (int c = 0; c < NC; ++c) {
        if (c < NC - 1) cp_wait<1>(); else cp_wait<0>();
        __syncthreads();
        if (c + 2 < NC) {
            SRC(c + 2);
            copy_chunk(base32 + ((c + 2) % 3) * STG, tid, sah, sstr);
        }
        compute_chunk(base32 + (c % 3) * STG, wbase + (uint32_t)c * 4096u,
                      lane, wr, wc, kh, acc);
    }
    __syncthreads();   // all warps done before stages are recycled
}

// dh: uint32_t* pre-offset to (buf, row0=mt*64, u32-col jt*4); row stride 128 u32
__device__ __forceinline__ void epilogue(float (&acc)[2][2][4], float* sG, const float* sb,
    float (&cst)[2], uint32_t* dh, float* h2fb,
    int tid, int lane, int wr, int wc, int kh, int jt)
{
    float* sp = sG + kh * 2560;
    #pragma unroll
    for (int mb = 0; mb < 2; ++mb)
        #pragma unroll
        for (int nb = 0; nb < 2; ++nb) {
            int r0 = wr + mb * 16 + (lane >> 2);
            int cc = wc + nb * 8 + (lane & 3) * 2;
            *(float2*)&sp[r0 * 40 + cc]       = make_float2(acc[mb][nb][0], acc[mb][nb][1]);
            *(float2*)&sp[(r0 + 8) * 40 + cc] = make_float2(acc[mb][nb][2], acc[mb][nb][3]);
        }
    __syncthreads();
    const int r = tid >> 2, ju = (tid & 3) * 2;
    float hv[2];
    #pragma unroll
    for (int u = 0; u < 2; ++u) {
        int jj = ju + u;
        float gf = sG[r * 40 + jj]      + sG[2560 + r * 40 + jj]      + sb[jj];
        float gi = sG[r * 40 + 8 + jj]  + sG[2560 + r * 40 + 8 + jj]  + sb[8 + jj];
        float gg = sG[r * 40 + 16 + jj] + sG[2560 + r * 40 + 16 + jj] + sb[16 + jj];
        float go = sG[r * 40 + 24 + jj] + sG[2560 + r * 40 + 24 + jj] + sb[24 + jj];
        float f = fsig(gf), i = fsig(gi), g = ftanh(gg), o = fsig(go);
        float c = f * cst[u] + i * g;
        cst[u] = c;
        hv[u] = o * ftanh(c);
    }
    __half a0 = __float2half(hv[0]), a1 = __float2half(hv[1]);
    dh[r * 128 + (ju >> 1)] = (uint32_t)__half_as_ushort(a0) | ((uint32_t)__half_as_ushort(a1) << 16);
    if (h2fb) {
        h2fb[(size_t)r * 256 + jt * 8 + ju]     = hv[0];
        h2fb[(size_t)r * 256 + jt * 8 + ju + 1] = hv[1];
    }
    __syncthreads();
}

__global__ void __launch_bounds__(NTH, 2)
lstm_mma_kernel(const float* __restrict__ b1, const float* __restrict__ b2,
                const float* __restrict__ Wout, const float* __restrict__ bout,
                float* __restrict__ out)
{
    extern __shared__ uint4 dsm[];
    __shared__ float s_b1[32], s_b2[32];

    const int tid = threadIdx.x, cta = blockIdx.x;
    const int warp = tid >> 5, lane = tid & 31;
    const int mt = cta >> 5, jt = cta & 31;
    const int kh = warp & 1;                       // 2(M:32) x 2(N:16) x 2(K-split)
    const int wr = ((warp >> 1) & 1) * 32, wc = (warp >> 2) * 16;
    uint32_t base32 = (sm32(dsm) + 1023u) & ~1023u;
    float* sG = (float*)((char*)dsm + ((base32 - sm32(dsm)) + SGOFF));

    if (tid < 32) {
        int gate = tid >> 3, u = tid & 7;
        s_b1[tid] = b1[gate * H_ + jt * 8 + u];
        s_b2[tid] = b2[gate * H_ + jt * 8 + u];
    }
    // ---- stage W into persistent smem (once) ----
    {
        const uint4* w1h = g_w1_h + (size_t)(jt * 32) * 48;
        const uint4* w2h = g_w2_h + (size_t)(jt * 32) * 64;
        for (int i = tid; i < 1536; i += NTH) {     // W1: 6 chunks x 32 rows x 8 gran
            int c = i >> 8, rg = i & 255, r = rg >> 3, g = rg & 7;
            cp16(base32 + W1OFF + (uint32_t)c * 4096u + (uint32_t)r * 128
                 + (uint32_t)((g ^ (r & 7)) << 4), w1h + (size_t)r * 48 + c * 8 + g);
        }
        for (int i = tid; i < 2048; i += NTH) {     // W2: 8 chunks x 32 rows x 8 gran
            int c = i >> 8, rg = i & 255, r = rg >> 3, g = rg & 7;
            cp16(base32 + W2OFF + (uint32_t)c * 4096u + (uint32_t)r * 128
                 + (uint32_t)((g ^ (r & 7)) << 4), w2h + (size_t)r * 64 + c * 8 + g);
        }
        cp_commit();
    }
    {   // zero this group's h rows
        int i = jt * NTH + tid;
        if (i < 4096) {
            int buf = i >> 11, rr = (i >> 5) & 63, g = i & 31;
            size_t idx = (size_t)buf * 16384 + (size_t)(mt * 64 + rr) * 32 + g;
            uint4 z = make_uint4(0, 0, 0, 0);
            g_h1_h[idx] = z; g_h2_h[idx] = z;
        }
    }
    cp_wait<0>();
    unsigned sense = 0;
    gbar(mt, sense);                               // group barrier #1 (syncs W staging too)

    float c1[2] = {0.f, 0.f}, c2[2] = {0.f, 0.f};

    for (int p = 0; p < 1025; ++p) {
        const bool do1 = p < 1024, do2 = p > 0;
        float acc1[2][2][4], acc2[2][2][4];

        const int rb1 = (p - 1) & 1;               // h1(p-1) buffer
        const int rb2 = p & 1;                     // h2(p-2) buffer
        const uint4* h1r = g_h1_h + ((size_t)rb1 * 512 + mt * 64) * 32;
        const uint4* h2r = g_h2_h + ((size_t)rb2 * 512 + mt * 64) * 32;

        if (do1) {
            const uint4* xh = g_x_h + ((size_t)p * 512 + mt * 64) * 16;
            #pragma unroll
            for (int mb = 0; mb < 2; ++mb)
                #pragma unroll
                for (int nb = 0; nb < 2; ++nb)
                    #pragma unroll
                    for (int e = 0; e < 4; ++e) acc1[mb][nb][e] = 0.f;
            gemm_prol<6,2,16,32>(base32, tid, xh, h1r);
            gemm_main<6,2,16,32>(base32, base32 + W1OFF, tid, lane, wr, wc, kh,
                                 xh, h1r, acc1);
        }
        if (do2) {
            #pragma unroll
            for (int mb = 0; mb < 2; ++mb)
                #pragma unroll
                for (int nb = 0; nb < 2; ++nb)
                    #pragma unroll
                    for (int e = 0; e < 4; ++e) acc2[mb][nb][e] = 0.f;
            gemm_prol<8,4,32,32>(base32, tid, h1r, h2r);
        }
        if (do1) {
            const int wb = p & 1;
            uint32_t* dh = (uint32_t*)(g_h1_h + ((size_t)wb * 512 + mt * 64) * 32) + jt * 4;
            epilogue(acc1, sG, s_b1, c1, dh, (float*)0, tid, lane, wr, wc, kh, jt);
        }
        if (do2) {
            gemm_main<8,4,32,32>(base32, base32 + W2OFF, tid, lane, wr, wc, kh,
                                 h1r, h2r, acc2);
            const int wb = (p - 1) & 1;
            uint32_t* dh = (uint32_t*)(g_h2_h + ((size_t)wb * 512 + mt * 64) * 32) + jt * 4;
            float* hb = (p == 1024) ? g_h2f + (size_t)(mt * 64) * 256 : (float*)0;
            epilogue(acc2, sG, s_b2, c2, dh, hb, tid, lane, wr, wc, kh, jt);
        }
        gbar(mt, sense);                           // group total 1026 barriers (even)
    }

    if (jt == 0 && tid < 64) {
        int row = mt * 64 + tid;
        float s = 0.f;
        #pragma unroll 8
        for (int k = 0; k < H_; ++k) s += g_h2f[(size_t)row * H_ + k] * Wout[k];
        out[row] = s + bout[0];
    }
}

// ---------------- prep: fp16 planes ----------------
__global__ void prep_x_kernel(const float* __restrict__ x) {
    long gid = (long)blockIdx.x * 256 + threadIdx.x;
    int g = (int)(gid & 15);
    int b = (int)((gid >> 4) & 511);
    int t = (int)(gid >> 13);
    const float* src = x + ((size_t)b * 1024 + t) * 128 + g * 8;
    float4 f0 = *(const float4*)src, f1 = *(const float4*)(src + 4);
    float v[8] = {f0.x, f0.y, f0.z, f0.w, f1.x, f1.y, f1.z, f1.w};
    size_t di = ((size_t)t * 512 + b) * 16 + g;
    g_x_h[di] = packh8(v);
}

template<int K, int L>
__global__ void prep_w_kernel(const float* __restrict__ W) {
    uint4* dhi = (L == 1) ? g_w1_h : g_w2_h;
    int gid = blockIdx.x * 256 + threadIdx.x;
    int kg = gid % (K / 8);
    int np = gid / (K / 8);                        // n' = jt*32 + gate*8 + u
    int jt = np >> 5, gate = (np >> 3) & 3, u = np & 7;
    int col = gate * 256 + jt * 8 + u;
    float v[8];
    #pragma unroll
    for (int e = 0; e < 8; ++e) v[e] = W[(size_t)(kg * 8 + e) * 1024 + col];
    dhi[(size_t)np * (K / 8) + kg] = packh8(v);
}

extern "C" void kernel_launch(void* const* d_in, const int* in_sizes, int n_in,
                              void* d_out, int out_size)
{
    (void)in_sizes; (void)n_in; (void)out_size;
    const float* x    = (const float*)d_in[0];
    const float* W1   = (const float*)d_in[1];
    const float* b1   = (const float*)d_in[2];
    const float* W2   = (const float*)d_in[3];
    const float* b2   = (const float*)d_in[4];
    const float* Wout = (const float*)d_in[5];
    const float* bout = (const float*)d_in[6];
    cudaFuncSetAttribute(lstm_mma_kernel, cudaFuncAttributeMaxDynamicSharedMemorySize, SMEM_DYN);
    prep_x_kernel<<<32768, 256>>>(x);
    prep_w_kernel<384, 1><<<192, 256>>>(W1);
    prep_w_kernel<512, 2><<<256, 256>>>(W2);
    lstm_mma_kernel<<<NCTA, NTH, SMEM_DYN>>>(b1, b2, Wout, bout, (float*)d_out);
}